// round 14
// baseline (speedup 1.0000x reference)
#include <cuda_runtime.h>
#include <cuda_bf16.h>

#define NN 100000
#define EMAX 6400000
#define F 32
#define SCAN_B 512
#define NBLK ((NN + SCAN_B - 1) / SCAN_B)   // 196
#define KEDGE 16

// Scratch (device globals)
__device__ int   g_cnt[NN];               // per-dst edge count (degree - 1)
__device__ int   g_row[NN + 1];           // CSR row_start (exclusive) + total
__device__ int   g_off[NN];               // scatter cursor
__device__ int   g_bsum[NBLK];
__device__ int   g_boff[NBLK];
__device__ int   g_csr[EMAX];             // src indices grouped (sorted) by dst
__device__ float g_dis[NN];               // deg^{-1/2}
__device__ float4 g_x4[NN];               // dis * x, padded to 4 (w=0)
__device__ float4 g_agg1[NN];             // layer-1 aggregation
__device__ float g_h1s[NN * F];           // dis * relu(l1)  (f32, self reads)
__device__ __nv_bfloat16 g_h1b[NN * F];   // bf16 gather payload
__device__ float g_agg2[NN * F];          // layer-2 aggregation (f32)
__device__ float g_ys[NN];                // dis * (h2 @ W3)
__device__ float g_acc3[NN];              // layer-3 aggregation

__device__ __forceinline__ void red4(float* p, float4 v) {
    asm volatile("red.global.add.v4.f32 [%0], {%1, %2, %3, %4};"
                 :: "l"(p), "f"(v.x), "f"(v.y), "f"(v.z), "f"(v.w) : "memory");
}

// Find d such that row[d] <= e < row[d+1]
__device__ __forceinline__ int find_row(int e) {
    int lo = 0, hi = NN;
    while (hi - lo > 1) {
        int mid = (lo + hi) >> 1;
        if (__ldg(&g_row[mid]) <= e) lo = mid; else hi = mid;
    }
    return lo;
}

// ---------------------------------------------------------------------------
__global__ void init_kernel() {
    int i = blockIdx.x * blockDim.x + threadIdx.x;
    if (i < NN * F) g_agg2[i] = 0.0f;
    if (i < NN) {
        g_agg1[i] = make_float4(0.f, 0.f, 0.f, 0.f);
        g_acc3[i] = 0.0f;
        g_cnt[i] = 0;
    }
}

__global__ void hist_kernel(const int* __restrict__ dst, int E) {
    int e = blockIdx.x * blockDim.x + threadIdx.x;
    if (e < E) atomicAdd(&g_cnt[dst[e]], 1);
}

__global__ void scan1_kernel() {
    __shared__ int s[SCAN_B];
    int t = threadIdx.x;
    int i = blockIdx.x * SCAN_B + t;
    int v = (i < NN) ? g_cnt[i] : 0;
    s[t] = v;
    __syncthreads();
#pragma unroll
    for (int o = 1; o < SCAN_B; o <<= 1) {
        int add = (t >= o) ? s[t - o] : 0;
        __syncthreads();
        s[t] += add;
        __syncthreads();
    }
    if (i < NN) g_row[i] = s[t];              // inclusive for now
    if (t == SCAN_B - 1) g_bsum[blockIdx.x] = s[t];
}

// Parallel Hillis-Steele exclusive scan of 196 block sums (single block, 256 thr)
__global__ void scan2_kernel() {
    __shared__ int s[256];
    int t = threadIdx.x;
    int v = (t < NBLK) ? g_bsum[t] : 0;
    s[t] = v;
    __syncthreads();
#pragma unroll
    for (int o = 1; o < 256; o <<= 1) {
        int add = (t >= o) ? s[t - o] : 0;
        __syncthreads();
        s[t] += add;
        __syncthreads();
    }
    if (t < NBLK) g_boff[t] = s[t] - v;       // exclusive
}

// Finalize exclusive row starts, cursors, dis, pre-scaled x
__global__ void scan3_kernel(const float* __restrict__ x, int E) {
    int i = blockIdx.x * blockDim.x + threadIdx.x;
    if (i >= NN) return;
    int cnt = g_cnt[i];
    int row = g_row[i] - cnt + g_boff[i / SCAN_B];
    g_row[i] = row;
    g_off[i] = row;
    if (i == NN - 1) g_row[NN] = row + cnt;   // == E
    float dis = rsqrtf((float)(cnt + 1));     // +1 self loop
    g_dis[i] = dis;
    float4 v;
    v.x = dis * __ldg(&x[i * 3 + 0]);
    v.y = dis * __ldg(&x[i * 3 + 1]);
    v.z = dis * __ldg(&x[i * 3 + 2]);
    v.w = 0.0f;
    g_x4[i] = v;
}

__global__ void csr_scatter(const int* __restrict__ src, const int* __restrict__ dst, int E) {
    int e = blockIdx.x * blockDim.x + threadIdx.x;
    if (e >= E) return;
    int d = __ldg(&dst[e]);
    int pos = atomicAdd(&g_off[d], 1);
    g_csr[pos] = __ldg(&src[e]);
}

// ---------------------------------------------------------------------------
// Layer 1: edge-parallel over sorted edges; thread owns KEDGE consecutive edges,
// combines same-dst messages in registers, emits one RED per run.
__global__ void l1_sorted(int E) {
    int t = blockIdx.x * blockDim.x + threadIdx.x;
    int e0 = t * KEDGE;
    if (e0 >= E) return;
    int eEnd = min(e0 + KEDGE, E);
    int d = find_row(e0);
    int row_end = __ldg(&g_row[d + 1]);
    float4 acc = make_float4(0.f, 0.f, 0.f, 0.f);
    for (int e = e0; e < eEnd; e++) {
        if (e >= row_end) {
            red4(reinterpret_cast<float*>(&g_agg1[d]), acc);
            acc = make_float4(0.f, 0.f, 0.f, 0.f);
            do { d++; row_end = __ldg(&g_row[d + 1]); } while (row_end <= e);
        }
        int s = __ldg(&g_csr[e]);
        float4 v = __ldg(&g_x4[s]);
        acc.x += v.x; acc.y += v.y; acc.z += v.z;
    }
    red4(reinterpret_cast<float*>(&g_agg1[d]), acc);
}

// Layer 1 node pass (unchanged): 8 threads per node
__global__ void l1_node(const float* __restrict__ W1, const float* __restrict__ b1) {
    int t = blockIdx.x * blockDim.x + threadIdx.x;
    if (t >= NN * 8) return;
    int n = t >> 3;
    int c = t & 7;
    float dis = g_dis[n];
    float4 a = g_agg1[n];
    float4 xs = g_x4[n];
    float a0 = dis * (a.x + xs.x);
    float a1 = dis * (a.y + xs.y);
    float a2 = dis * (a.z + xs.z);
    int f0 = c * 4;
    float4 o;
    o.x = dis * fmaxf(0.0f, __ldg(&b1[f0 + 0]) + a0 * __ldg(&W1[0 * F + f0 + 0]) + a1 * __ldg(&W1[1 * F + f0 + 0]) + a2 * __ldg(&W1[2 * F + f0 + 0]));
    o.y = dis * fmaxf(0.0f, __ldg(&b1[f0 + 1]) + a0 * __ldg(&W1[0 * F + f0 + 1]) + a1 * __ldg(&W1[1 * F + f0 + 1]) + a2 * __ldg(&W1[2 * F + f0 + 1]));
    o.z = dis * fmaxf(0.0f, __ldg(&b1[f0 + 2]) + a0 * __ldg(&W1[0 * F + f0 + 2]) + a1 * __ldg(&W1[1 * F + f0 + 2]) + a2 * __ldg(&W1[2 * F + f0 + 2]));
    o.w = dis * fmaxf(0.0f, __ldg(&b1[f0 + 3]) + a0 * __ldg(&W1[0 * F + f0 + 3]) + a1 * __ldg(&W1[1 * F + f0 + 3]) + a2 * __ldg(&W1[2 * F + f0 + 3]));
    *reinterpret_cast<float4*>(&g_h1s[n * F + f0]) = o;

    __nv_bfloat162 p0 = __floats2bfloat162_rn(o.x, o.y);
    __nv_bfloat162 p1 = __floats2bfloat162_rn(o.z, o.w);
    uint2 packed;
    packed.x = *reinterpret_cast<unsigned int*>(&p0);
    packed.y = *reinterpret_cast<unsigned int*>(&p1);
    *reinterpret_cast<uint2*>(&g_h1b[n * F + f0]) = packed;
}

// ---------------------------------------------------------------------------
// Layer 2: 8-lane teams; team owns KEDGE sorted edges; lane c accumulates
// float4 feature chunk c in registers; RED once per dst-run.
__global__ void l2_sorted(int E) {
    long long tt = (long long)blockIdx.x * blockDim.x + threadIdx.x;
    int team = (int)(tt >> 3);
    int c = (int)(tt & 7);
    int e0 = team * KEDGE;
    if (e0 >= E) return;
    int eEnd = min(e0 + KEDGE, E);
    int d = find_row(e0);
    int row_end = __ldg(&g_row[d + 1]);
    float4 acc = make_float4(0.f, 0.f, 0.f, 0.f);
    for (int e = e0; e < eEnd; e++) {
        if (e >= row_end) {
            red4(&g_agg2[d * F + c * 4], acc);
            acc = make_float4(0.f, 0.f, 0.f, 0.f);
            do { d++; row_end = __ldg(&g_row[d + 1]); } while (row_end <= e);
        }
        int s = __ldg(&g_csr[e]);
        uint2 pk = __ldg(reinterpret_cast<const uint2*>(&g_h1b[s * F + c * 4]));
        __nv_bfloat162 p0 = *reinterpret_cast<__nv_bfloat162*>(&pk.x);
        __nv_bfloat162 p1 = *reinterpret_cast<__nv_bfloat162*>(&pk.y);
        float2 f0 = __bfloat1622float2(p0);
        float2 f1 = __bfloat1622float2(p1);
        acc.x += f0.x; acc.y += f0.y; acc.z += f1.x; acc.w += f1.y;
    }
    red4(&g_agg2[d * F + c * 4], acc);
}

// Layer 2+3 node pass (one warp per node, lane = feature)
__global__ void l2l3_node(const float* __restrict__ W2, const float* __restrict__ b2,
                          const float* __restrict__ W3) {
    __shared__ float sW2[F * F];
    __shared__ float sb2[F];
    __shared__ float sW3[F];
    for (int i = threadIdx.x; i < F * F; i += blockDim.x) sW2[i] = __ldg(&W2[i]);
    if (threadIdx.x < F) { sb2[threadIdx.x] = __ldg(&b2[threadIdx.x]); sW3[threadIdx.x] = __ldg(&W3[threadIdx.x]); }
    __syncthreads();

    int gw = (blockIdx.x * blockDim.x + threadIdx.x) >> 5;
    int lane = threadIdx.x & 31;
    if (gw >= NN) return;
    int n = gw;
    float dis = g_dis[n];
    float inv = dis * (g_agg2[n * F + lane] + g_h1s[n * F + lane]);
    float acc = sb2[lane];
#pragma unroll
    for (int k = 0; k < F; k++) {
        float hv = __shfl_sync(0xFFFFFFFFu, inv, k);
        acc += hv * sW2[k * F + lane];
    }
    float h2 = fmaxf(0.0f, acc);
    float part = h2 * sW3[lane];
#pragma unroll
    for (int o = 16; o > 0; o >>= 1)
        part += __shfl_xor_sync(0xFFFFFFFFu, part, o);
    if (lane == 0) g_ys[n] = dis * part;
}

// ---------------------------------------------------------------------------
// Layer 3: edge-parallel scalar over sorted edges, run-combined atomics
__global__ void l3_sorted(int E) {
    int t = blockIdx.x * blockDim.x + threadIdx.x;
    int e0 = t * KEDGE;
    if (e0 >= E) return;
    int eEnd = min(e0 + KEDGE, E);
    int d = find_row(e0);
    int row_end = __ldg(&g_row[d + 1]);
    float acc = 0.0f;
    for (int e = e0; e < eEnd; e++) {
        if (e >= row_end) {
            atomicAdd(&g_acc3[d], acc);
            acc = 0.0f;
            do { d++; row_end = __ldg(&g_row[d + 1]); } while (row_end <= e);
        }
        int s = __ldg(&g_csr[e]);
        acc += __ldg(&g_ys[s]);
    }
    atomicAdd(&g_acc3[d], acc);
}

__global__ void finalize_kernel(const float* __restrict__ b3, float* __restrict__ out) {
    int n = blockIdx.x * blockDim.x + threadIdx.x;
    if (n >= NN) return;
    out[n] = __ldg(&b3[0]) + g_dis[n] * (g_acc3[n] + g_ys[n]);
}

// ---------------------------------------------------------------------------
extern "C" void kernel_launch(void* const* d_in, const int* in_sizes, int n_in,
                              void* d_out, int out_size) {
    const float* x  = (const float*)d_in[0];
    const int*   ei = (const int*)d_in[1];
    const float* W1 = (const float*)d_in[2];
    const float* b1 = (const float*)d_in[3];
    const float* W2 = (const float*)d_in[4];
    const float* b2 = (const float*)d_in[5];
    const float* W3 = (const float*)d_in[6];
    const float* b3 = (const float*)d_in[7];
    float* out = (float*)d_out;

    int E = in_sizes[1] / 2;
    const int* src = ei;
    const int* dst = ei + E;

    const int B = 256;
    init_kernel<<<(NN * F + B - 1) / B, B>>>();
    hist_kernel<<<(E + B - 1) / B, B>>>(dst, E);
    scan1_kernel<<<NBLK, SCAN_B>>>();
    scan2_kernel<<<1, 256>>>();
    scan3_kernel<<<(NN + B - 1) / B, B>>>(x, E);
    csr_scatter<<<(E + B - 1) / B, B>>>(src, dst, E);

    int nThread1 = (E + KEDGE - 1) / KEDGE;
    l1_sorted<<<(nThread1 + B - 1) / B, B>>>(E);
    l1_node<<<(NN * 8 + B - 1) / B, B>>>(W1, b1);

    long long nThread2 = (long long)nThread1 * 8;
    l2_sorted<<<(unsigned)((nThread2 + B - 1) / B), B>>>(E);
    l2l3_node<<<(NN * 32 + B - 1) / B, B>>>(W2, b2, W3);

    l3_sorted<<<(nThread1 + B - 1) / B, B>>>(E);
    finalize_kernel<<<(NN + B - 1) / B, B>>>(b3, out);
}